// round 14
// baseline (speedup 1.0000x reference)
#include <cuda_runtime.h>
#include <cstdint>

#define NN       8192
#define THREADS  896                 // 28 warps per block
#define SCAN_T   512                 // threads used for the cb block scan
#define GBLOCKS  148                 // 1 block per SM, single wave

__device__ float g_zero = 0.0f;

// ---------------------------------------------------------------------------
// One row per WARP, fully coalesced loads, FULLY UNROLLED chunk loop.
// 16 chunks of 512 elements; lane l owns float4s {0,32,64,96}+l per chunk
// (each LDG.128 = 512B contiguous). Four interleaved warp scans per chunk;
// 4 independent accumulators. Full unroll: no rotation MOVs, no loop
// branches, immediate address offsets, compile-time N-1 predicate (emitted
// only in chunk 15). Zero block barriers in the main loop; cb in smem.
// ---------------------------------------------------------------------------
__global__ void __launch_bounds__(THREADS, 1)
row_w1_kernel(const float* __restrict__ x, const float* __restrict__ bary,
              float* __restrict__ out, int D, int RW)
{
    __shared__ __align__(16) float cb[NN];
    __shared__ float ws[SCAN_T / 32];

    const int t    = threadIdx.x;
    const int lane = t & 31;
    const int wid  = t >> 5;

    // ---- build cb in smem: threads 0..511, 16 elements each ----
    float4 q0, q1, q2, q3;
    float p00,p01,p02,p03,p04,p05,p06,p07,p08,p09,p10,p11,p12,p13,p14,p15;
    float s = 0.0f;
    if (t < SCAN_T) {
        const float4* bp = reinterpret_cast<const float4*>(bary) + t * 4;
        q0 = bp[0]; q1 = bp[1]; q2 = bp[2]; q3 = bp[3];

        p00 = q0.x;
        p01 = p00 + q0.y;
        p02 = p01 + q0.z;
        p03 = p02 + q0.w;
        p04 = p03 + q1.x;
        p05 = p04 + q1.y;
        p06 = p05 + q1.z;
        p07 = p06 + q1.w;
        p08 = p07 + q2.x;
        p09 = p08 + q2.y;
        p10 = p09 + q2.z;
        p11 = p10 + q2.w;
        p12 = p11 + q3.x;
        p13 = p12 + q3.y;
        p14 = p13 + q3.z;
        p15 = p14 + q3.w;

        s = p15;
        #pragma unroll
        for (int o = 1; o < 32; o <<= 1) {
            float y = __shfl_up_sync(0xFFFFFFFFu, s, o);
            if (lane >= o) s += y;
        }
        if (lane == 31) ws[wid] = s;
    }
    __syncthreads();
    if (t < SCAN_T) {
        float w = (lane < SCAN_T / 32) ? ws[lane] : 0.0f;
        #pragma unroll
        for (int o = 1; o < SCAN_T / 32; o <<= 1) {
            float y = __shfl_up_sync(0xFFFFFFFFu, w, o);
            if (lane >= o) w += y;
        }
        float woff = (wid > 0) ? __shfl_sync(0xFFFFFFFFu, w, wid - 1) : 0.0f;
        float off = woff + (s - p15);

        float* c = cb + t * 16;
        c[0]  = off + p00;  c[1]  = off + p01;  c[2]  = off + p02;  c[3]  = off + p03;
        c[4]  = off + p04;  c[5]  = off + p05;  c[6]  = off + p06;  c[7]  = off + p07;
        c[8]  = off + p08;  c[9]  = off + p09;  c[10] = off + p10;  c[11] = off + p11;
        c[12] = off + p12;  c[13] = off + p13;  c[14] = off + p14;  c[15] = off + p15;
    }
    // block 0 also writes bary into out[1..N]
    if (blockIdx.x == 0) {
        for (int i = t; i < NN; i += THREADS)
            out[1 + i] = bary[i];
    }
    __syncthreads();

    // ---- main: one row per warp, zero block barriers, coalesced loads ----
    const int row = blockIdx.x * RW + wid;
    if (wid < RW && row < D) {
        const float4* p =
            reinterpret_cast<const float4*>(x + (size_t)row * NN) + lane;
        const float4* cc = reinterpret_cast<const float4*>(cb) + lane;

        float offset = 0.0f;
        float acc0 = 0.0f, acc1 = 0.0f, acc2 = 0.0f, acc3 = 0.0f;

        #pragma unroll
        for (int c = 0; c < 16; ++c) {
            // loads with compile-time immediate offsets
            const float4* pc = p + c * 128;
            float4 v0 = pc[0], v1 = pc[32], v2 = pc[64], v3 = pc[96];

            // in-lane inclusive scans of each sub-block's 4 elements
            float a0 = v0.x, a1 = a0 + v0.y, a2 = a1 + v0.z, a3 = a2 + v0.w;
            float b0 = v1.x, b1 = b0 + v1.y, b2 = b1 + v1.z, b3 = b2 + v1.w;
            float d0 = v2.x, d1 = d0 + v2.y, d2 = d1 + v2.z, d3 = d2 + v2.w;
            float e0 = v3.x, e1 = e0 + v3.y, e2 = e1 + v3.z, e3 = e2 + v3.w;

            // four simultaneous warp inclusive scans of lane sums
            float sA = a3, sB = b3, sD = d3, sE = e3;
            #pragma unroll
            for (int o = 1; o < 32; o <<= 1) {
                float yA = __shfl_up_sync(0xFFFFFFFFu, sA, o);
                float yB = __shfl_up_sync(0xFFFFFFFFu, sB, o);
                float yD = __shfl_up_sync(0xFFFFFFFFu, sD, o);
                float yE = __shfl_up_sync(0xFFFFFFFFu, sE, o);
                if (lane >= o) { sA += yA; sB += yB; sD += yD; sE += yE; }
            }
            float TA = __shfl_sync(0xFFFFFFFFu, sA, 31);
            float TB = __shfl_sync(0xFFFFFFFFu, sB, 31);
            float TD = __shfl_sync(0xFFFFFFFFu, sD, 31);
            float TE = __shfl_sync(0xFFFFFFFFu, sE, 31);

            float baseA = offset + (sA - a3);
            float baseB = offset + TA + (sB - b3);
            float baseD = offset + TA + TB + (sD - d3);
            float baseE = offset + TA + TB + TD + (sE - e3);

            // cb for this chunk (coalesced LDS.128, immediate offsets)
            const float4* cp = cc + c * 128;
            float4 c0 = cp[0], c1 = cp[32], c2 = cp[64], c3 = cp[96];

            // four independent accumulation chains
            acc0 += fabsf(baseA + a0 - c0.x);
            acc0 += fabsf(baseA + a1 - c0.y);
            acc0 += fabsf(baseA + a2 - c0.z);
            acc0 += fabsf(baseA + a3 - c0.w);
            acc1 += fabsf(baseB + b0 - c1.x);
            acc1 += fabsf(baseB + b1 - c1.y);
            acc1 += fabsf(baseB + b2 - c1.z);
            acc1 += fabsf(baseB + b3 - c1.w);
            acc2 += fabsf(baseD + d0 - c2.x);
            acc2 += fabsf(baseD + d1 - c2.y);
            acc2 += fabsf(baseD + d2 - c2.z);
            acc2 += fabsf(baseD + d3 - c2.w);
            acc3 += fabsf(baseE + e0 - c3.x);
            acc3 += fabsf(baseE + e1 - c3.y);
            acc3 += fabsf(baseE + e2 - c3.z);
            if (c != 15) {
                acc3 += fabsf(baseE + e3 - c3.w);
            } else if (lane != 31) {           // exclude global element N-1
                acc3 += fabsf(baseE + e3 - c3.w);
            }

            offset = offset + TA + TB + TD + TE;
        }

        float acc = (acc0 + acc1) + (acc2 + acc3);

        // warp reduction + one atomic per warp
        #pragma unroll
        for (int o = 16; o > 0; o >>= 1)
            acc += __shfl_down_sync(0xFFFFFFFFu, acc, o);
        if (lane == 0)
            atomicAdd(out, acc);
    }
}

// ---------------------------------------------------------------------------
extern "C" void kernel_launch(void* const* d_in, const int* in_sizes, int n_in,
                              void* d_out, int out_size)
{
    const float* x    = (const float*)d_in[0];   // [D, N] f32
    const float* bary = (const float*)d_in[1];   // [N] f32
    float* out = (float*)d_out;

    const int N = in_sizes[1];
    const int D = in_sizes[0] / N;
    (void)n_in; (void)out_size; (void)N;

    // out[0] = 0 via tiny D2D copy (stream-ordered before the kernel's atomics)
    void* zp = nullptr;
    cudaGetSymbolAddress(&zp, g_zero);
    cudaMemcpyAsync(out, zp, sizeof(float), cudaMemcpyDeviceToDevice, 0);

    const int grid = GBLOCKS;
    const int rw   = (D + grid - 1) / grid;      // rows per block (<= 28)
    row_w1_kernel<<<grid, THREADS>>>(x, bary, out, D, rw);
}